// round 4
// baseline (speedup 1.0000x reference)
#include <cuda_runtime.h>
#include <cuda_bf16.h>

#define N_NODES 100000
#define E_EDGES 1600000
#define DIN     256
#define DHID    64
#define DOUT    40
#define PROP_STEPS 16

// Scratch (allocation-free rule: __device__ globals)
__device__ float g_Y0[N_NODES * DHID];
__device__ float g_Y1[N_NODES * DHID];
__device__ float g_src[N_NODES * DHID];
__device__ int2  g_epack[E_EDGES];          // packed (col, val_bits): 1 LDG.128 = 2 edges
__device__ int   g_row_ptr[N_NODES + 1];

// ---------------------------------------------------------------------------
// Kernel 1: CSR row pointers from sorted edge_row via per-thread lower_bound
// ---------------------------------------------------------------------------
__global__ void build_rowptr_kernel(const int* __restrict__ edge_row) {
    int r = blockIdx.x * blockDim.x + threadIdx.x;
    if (r > N_NODES) return;
    int lo = 0, hi = E_EDGES;
    while (lo < hi) {
        int mid = (lo + hi) >> 1;
        if (edge_row[mid] < r) lo = mid + 1; else hi = mid;
    }
    g_row_ptr[r] = lo;
}

// ---------------------------------------------------------------------------
// Kernel 1b: pack (col, val) pairs so the prop loop does 1 LDG per 2 edges
// ---------------------------------------------------------------------------
__global__ void pack_edges_kernel(const int* __restrict__ ecol,
                                  const float* __restrict__ evalv) {
    int i = blockIdx.x * blockDim.x + threadIdx.x;
    if (i < E_EDGES)
        g_epack[i] = make_int2(ecol[i], __float_as_int(evalv[i]));
}

// ---------------------------------------------------------------------------
// Kernel 2: h = x @ W1 + b1 ; Y0 = h ; src = 0.5 * diag * h
// ---------------------------------------------------------------------------
__global__ __launch_bounds__(256) void gemm1_kernel(
    const float* __restrict__ x, const float* __restrict__ W1,
    const float* __restrict__ b1, const float* __restrict__ diag)
{
    __shared__ float xs[64][33];
    __shared__ float ws[32][64];

    const int tid = threadIdx.x;
    const int ty = tid >> 4;
    const int tx = tid & 15;
    const int row0 = blockIdx.x * 64;

    float acc[4][4];
    #pragma unroll
    for (int i = 0; i < 4; i++)
        #pragma unroll
        for (int j = 0; j < 4; j++) acc[i][j] = 0.f;

    for (int k0 = 0; k0 < DIN; k0 += 32) {
        #pragma unroll
        for (int i = 0; i < 8; i++) {
            int idx = tid + i * 256;
            int r = idx >> 5, kk = idx & 31;
            int gr = row0 + r;
            xs[r][kk] = (gr < N_NODES) ? x[gr * DIN + k0 + kk] : 0.f;
        }
        #pragma unroll
        for (int i = 0; i < 8; i++) {
            int idx = tid + i * 256;
            int kk = idx >> 6, c = idx & 63;
            ws[kk][c] = W1[(k0 + kk) * DHID + c];
        }
        __syncthreads();

        #pragma unroll
        for (int kk = 0; kk < 32; kk++) {
            float a0 = xs[ty * 4 + 0][kk];
            float a1 = xs[ty * 4 + 1][kk];
            float a2 = xs[ty * 4 + 2][kk];
            float a3 = xs[ty * 4 + 3][kk];
            float w0 = ws[kk][tx * 4 + 0];
            float w1 = ws[kk][tx * 4 + 1];
            float w2 = ws[kk][tx * 4 + 2];
            float w3 = ws[kk][tx * 4 + 3];
            acc[0][0] += a0 * w0; acc[0][1] += a0 * w1; acc[0][2] += a0 * w2; acc[0][3] += a0 * w3;
            acc[1][0] += a1 * w0; acc[1][1] += a1 * w1; acc[1][2] += a1 * w2; acc[1][3] += a1 * w3;
            acc[2][0] += a2 * w0; acc[2][1] += a2 * w1; acc[2][2] += a2 * w2; acc[2][3] += a2 * w3;
            acc[3][0] += a3 * w0; acc[3][1] += a3 * w1; acc[3][2] += a3 * w2; acc[3][3] += a3 * w3;
        }
        __syncthreads();
    }

    #pragma unroll
    for (int i = 0; i < 4; i++) {
        int gr = row0 + ty * 4 + i;
        if (gr < N_NODES) {
            float dv = 0.5f * diag[gr];
            #pragma unroll
            for (int j = 0; j < 4; j++) {
                int c = tx * 4 + j;
                float h = acc[i][j] + b1[c];
                g_Y0[gr * DHID + c]  = h;
                g_src[gr * DHID + c] = dv * h;
            }
        }
    }
}

// ---------------------------------------------------------------------------
// Kernel 3: one propagation step. One warp per row; lane owns 2 columns.
// 2 edges per packed LDG.128; 4 edges per loop iter => 1.5 LDG/edge (LSU-bound).
// ---------------------------------------------------------------------------
__global__ __launch_bounds__(256) void prop_kernel(int phase)
{
    const float2* __restrict__ Yin  = (const float2*)(phase ? g_Y1 : g_Y0);
    float2*       __restrict__ Yout = (float2*)      (phase ? g_Y0 : g_Y1);

    int w = (blockIdx.x * blockDim.x + threadIdx.x) >> 5;
    if (w >= N_NODES) return;
    int lane = threadIdx.x & 31;

    int e   = g_row_ptr[w];
    int end = g_row_ptr[w + 1];

    float ax = 0.f, ay = 0.f;

    // Align to even edge index so int4 loads hit 16B boundaries
    if ((e & 1) && e < end) {
        int2 p = g_epack[e];
        float v = __int_as_float(p.y);
        float2 y = Yin[p.x * (DHID / 2) + lane];
        ax += v * y.x; ay += v * y.y;
        e++;
    }

    // Main loop: 4 edges (2 x LDG.128 + 4 gather LDG.64)
    for (; e + 4 <= end; e += 4) {
        int4 p0 = *(const int4*)&g_epack[e];
        int4 p1 = *(const int4*)&g_epack[e + 2];
        float2 y0 = Yin[p0.x * (DHID / 2) + lane];
        float2 y1 = Yin[p0.z * (DHID / 2) + lane];
        float2 y2 = Yin[p1.x * (DHID / 2) + lane];
        float2 y3 = Yin[p1.z * (DHID / 2) + lane];
        float v0 = __int_as_float(p0.y);
        float v1 = __int_as_float(p0.w);
        float v2 = __int_as_float(p1.y);
        float v3 = __int_as_float(p1.w);
        ax += v0 * y0.x + v1 * y1.x + v2 * y2.x + v3 * y3.x;
        ay += v0 * y0.y + v1 * y1.y + v2 * y2.y + v3 * y3.y;
    }
    // Pair tail (2 edges)
    if (e + 2 <= end) {
        int4 p0 = *(const int4*)&g_epack[e];
        float2 y0 = Yin[p0.x * (DHID / 2) + lane];
        float2 y1 = Yin[p0.z * (DHID / 2) + lane];
        ax += __int_as_float(p0.y) * y0.x + __int_as_float(p0.w) * y1.x;
        ay += __int_as_float(p0.y) * y0.y + __int_as_float(p0.w) * y1.y;
        e += 2;
    }
    // Single tail
    if (e < end) {
        int2 p = g_epack[e];
        float v = __int_as_float(p.y);
        float2 y = Yin[p.x * (DHID / 2) + lane];
        ax += v * y.x; ay += v * y.y;
    }

    float2 yr = Yin[w * (DHID / 2) + lane];
    float2 s  = ((const float2*)g_src)[w * (DHID / 2) + lane];
    float2 o;
    o.x = 0.5f * (yr.x + ax) + s.x;
    o.y = 0.5f * (yr.y + ay) + s.y;
    Yout[w * (DHID / 2) + lane] = o;
}

// ---------------------------------------------------------------------------
// Kernel 4: out = relu(Y) @ W2 + b2.
// ---------------------------------------------------------------------------
__global__ __launch_bounds__(256) void mlp2_kernel(
    const float* __restrict__ W2, const float* __restrict__ b2,
    float* __restrict__ out)
{
    __shared__ float w2s[64][41];
    __shared__ float ys[64][65];
    __shared__ float b2s[DOUT];

    const int tid = threadIdx.x;
    const int row0 = blockIdx.x * 64;

    for (int idx = tid; idx < DHID * DOUT; idx += 256)
        w2s[idx / DOUT][idx % DOUT] = W2[idx];
    if (tid < DOUT) b2s[tid] = b2[tid];

    #pragma unroll
    for (int i = 0; i < 16; i++) {
        int idx = tid + i * 256;
        int r = idx >> 6, c = idx & 63;
        int gr = row0 + r;
        ys[r][c] = (gr < N_NODES) ? fmaxf(g_Y0[gr * DHID + c], 0.f) : 0.f;
    }
    __syncthreads();

    const int row = tid >> 2;
    const int cg  = tid & 3;
    float acc[10];
    #pragma unroll
    for (int i = 0; i < 10; i++) acc[i] = b2s[cg * 10 + i];

    #pragma unroll 8
    for (int j = 0; j < DHID; j++) {
        float yv = ys[row][j];
        #pragma unroll
        for (int i = 0; i < 10; i++)
            acc[i] += yv * w2s[j][cg * 10 + i];
    }

    int gr = row0 + row;
    if (gr < N_NODES) {
        #pragma unroll
        for (int i = 0; i < 10; i++)
            out[gr * DOUT + cg * 10 + i] = acc[i];
    }
}

// ---------------------------------------------------------------------------
extern "C" void kernel_launch(void* const* d_in, const int* in_sizes, int n_in,
                              void* d_out, int out_size)
{
    const float* x     = (const float*)d_in[0];
    const int*   erow  = (const int*)  d_in[1];
    const int*   ecol  = (const int*)  d_in[2];
    const float* evalv = (const float*)d_in[3];
    const float* diag  = (const float*)d_in[4];
    const float* W1    = (const float*)d_in[5];
    const float* b1    = (const float*)d_in[6];
    const float* W2    = (const float*)d_in[7];
    const float* b2    = (const float*)d_in[8];
    float* out = (float*)d_out;

    build_rowptr_kernel<<<(N_NODES + 1 + 255) / 256, 256>>>(erow);
    pack_edges_kernel<<<(E_EDGES + 255) / 256, 256>>>(ecol, evalv);

    int gemm_blocks = (N_NODES + 63) / 64;
    gemm1_kernel<<<gemm_blocks, 256>>>(x, W1, b1, diag);

    int prop_blocks = (N_NODES * 32 + 255) / 256;   // one warp per row
    for (int s = 0; s < PROP_STEPS; s++) {
        prop_kernel<<<prop_blocks, 256>>>(s & 1);
    }

    mlp2_kernel<<<gemm_blocks, 256>>>(W2, b2, out);
}

// round 5
// speedup vs baseline: 1.0654x; 1.0654x over previous
#include <cuda_runtime.h>
#include <cuda_bf16.h>

#define N_NODES 100000
#define E_EDGES 1600000
#define DIN     256
#define DHID    64
#define DOUT    40
#define PROP_STEPS 16
#define ROWS_PER_BLOCK 8
#define EDGE_CAP 2048          // smem capacity (int2 = 16 KB); Poisson(16)x8 never exceeds

// Scratch (allocation-free rule: __device__ globals)
__device__ float g_Y0[N_NODES * DHID];
__device__ float g_Y1[N_NODES * DHID];
__device__ float g_src[N_NODES * DHID];
__device__ int2  g_epack[E_EDGES];          // packed (col, val_bits)
__device__ int   g_row_ptr[N_NODES + 1];

// ---------------------------------------------------------------------------
// Kernel 1: CSR row pointers from sorted edge_row via per-thread lower_bound
// ---------------------------------------------------------------------------
__global__ void build_rowptr_kernel(const int* __restrict__ edge_row) {
    int r = blockIdx.x * blockDim.x + threadIdx.x;
    if (r > N_NODES) return;
    int lo = 0, hi = E_EDGES;
    while (lo < hi) {
        int mid = (lo + hi) >> 1;
        if (edge_row[mid] < r) lo = mid + 1; else hi = mid;
    }
    g_row_ptr[r] = lo;
}

// ---------------------------------------------------------------------------
// Kernel 1b: pack (col, val) pairs
// ---------------------------------------------------------------------------
__global__ void pack_edges_kernel(const int* __restrict__ ecol,
                                  const float* __restrict__ evalv) {
    int i = blockIdx.x * blockDim.x + threadIdx.x;
    if (i < E_EDGES)
        g_epack[i] = make_int2(ecol[i], __float_as_int(evalv[i]));
}

// ---------------------------------------------------------------------------
// Kernel 2: h = x @ W1 + b1 ; Y0 = h ; src = 0.5 * diag * h
// ---------------------------------------------------------------------------
__global__ __launch_bounds__(256) void gemm1_kernel(
    const float* __restrict__ x, const float* __restrict__ W1,
    const float* __restrict__ b1, const float* __restrict__ diag)
{
    __shared__ float xs[64][33];
    __shared__ float ws[32][64];

    const int tid = threadIdx.x;
    const int ty = tid >> 4;
    const int tx = tid & 15;
    const int row0 = blockIdx.x * 64;

    float acc[4][4];
    #pragma unroll
    for (int i = 0; i < 4; i++)
        #pragma unroll
        for (int j = 0; j < 4; j++) acc[i][j] = 0.f;

    for (int k0 = 0; k0 < DIN; k0 += 32) {
        #pragma unroll
        for (int i = 0; i < 8; i++) {
            int idx = tid + i * 256;
            int r = idx >> 5, kk = idx & 31;
            int gr = row0 + r;
            xs[r][kk] = (gr < N_NODES) ? x[gr * DIN + k0 + kk] : 0.f;
        }
        #pragma unroll
        for (int i = 0; i < 8; i++) {
            int idx = tid + i * 256;
            int kk = idx >> 6, c = idx & 63;
            ws[kk][c] = W1[(k0 + kk) * DHID + c];
        }
        __syncthreads();

        #pragma unroll
        for (int kk = 0; kk < 32; kk++) {
            float a0 = xs[ty * 4 + 0][kk];
            float a1 = xs[ty * 4 + 1][kk];
            float a2 = xs[ty * 4 + 2][kk];
            float a3 = xs[ty * 4 + 3][kk];
            float w0 = ws[kk][tx * 4 + 0];
            float w1 = ws[kk][tx * 4 + 1];
            float w2 = ws[kk][tx * 4 + 2];
            float w3 = ws[kk][tx * 4 + 3];
            acc[0][0] += a0 * w0; acc[0][1] += a0 * w1; acc[0][2] += a0 * w2; acc[0][3] += a0 * w3;
            acc[1][0] += a1 * w0; acc[1][1] += a1 * w1; acc[1][2] += a1 * w2; acc[1][3] += a1 * w3;
            acc[2][0] += a2 * w0; acc[2][1] += a2 * w1; acc[2][2] += a2 * w2; acc[2][3] += a2 * w3;
            acc[3][0] += a3 * w0; acc[3][1] += a3 * w1; acc[3][2] += a3 * w2; acc[3][3] += a3 * w3;
        }
        __syncthreads();
    }

    #pragma unroll
    for (int i = 0; i < 4; i++) {
        int gr = row0 + ty * 4 + i;
        if (gr < N_NODES) {
            float dv = 0.5f * diag[gr];
            #pragma unroll
            for (int j = 0; j < 4; j++) {
                int c = tx * 4 + j;
                float h = acc[i][j] + b1[c];
                g_Y0[gr * DHID + c]  = h;
                g_src[gr * DHID + c] = dv * h;
            }
        }
    }
}

// ---------------------------------------------------------------------------
// Kernel 3: one propagation step.
// Block = 8 consecutive rows = one contiguous edge range (rows sorted).
// Stage all (col,val) pairs into smem cooperatively (coalesced, 1 LDG / 32
// edges), then each warp processes its row with LDS broadcasts + 1 gather
// LDG per edge. LDG/edge drops 3 -> ~1.03 with uniform control flow.
// ---------------------------------------------------------------------------
__global__ __launch_bounds__(256) void prop_kernel(int phase)
{
    const float2* __restrict__ Yin  = (const float2*)(phase ? g_Y1 : g_Y0);
    float2*       __restrict__ Yout = (float2*)      (phase ? g_Y0 : g_Y1);

    __shared__ int2 se[EDGE_CAP];
    __shared__ int  sptr[ROWS_PER_BLOCK + 1];

    const int tid  = threadIdx.x;
    const int wid  = tid >> 5;
    const int lane = tid & 31;
    const int r0   = blockIdx.x * ROWS_PER_BLOCK;

    if (tid <= ROWS_PER_BLOCK)
        sptr[tid] = g_row_ptr[r0 + tid];
    __syncthreads();

    const int eb  = sptr[0];
    const int cnt = sptr[ROWS_PER_BLOCK] - eb;

    const int w = r0 + wid;                 // this warp's row
    float ax = 0.f, ay = 0.f;

    if (cnt <= EDGE_CAP) {
        // cooperative coalesced staging of the block's whole edge range
        for (int i = tid; i < cnt; i += 256)
            se[i] = g_epack[eb + i];
        __syncthreads();

        int e   = sptr[wid]     - eb;
        int end = sptr[wid + 1] - eb;

        for (; e + 4 <= end; e += 4) {
            int2 p0 = se[e], p1 = se[e + 1], p2 = se[e + 2], p3 = se[e + 3];
            float2 y0 = Yin[p0.x * (DHID / 2) + lane];
            float2 y1 = Yin[p1.x * (DHID / 2) + lane];
            float2 y2 = Yin[p2.x * (DHID / 2) + lane];
            float2 y3 = Yin[p3.x * (DHID / 2) + lane];
            float v0 = __int_as_float(p0.y);
            float v1 = __int_as_float(p1.y);
            float v2 = __int_as_float(p2.y);
            float v3 = __int_as_float(p3.y);
            ax += v0 * y0.x + v1 * y1.x + v2 * y2.x + v3 * y3.x;
            ay += v0 * y0.y + v1 * y1.y + v2 * y2.y + v3 * y3.y;
        }
        for (; e < end; e++) {
            int2 p = se[e];
            float v = __int_as_float(p.y);
            float2 y = Yin[p.x * (DHID / 2) + lane];
            ax += v * y.x; ay += v * y.y;
        }
    } else {
        // fallback: direct global loads (essentially unreachable)
        int e   = sptr[wid];
        int end = sptr[wid + 1];
        for (; e < end; e++) {
            int2 p = g_epack[e];
            float v = __int_as_float(p.y);
            float2 y = Yin[p.x * (DHID / 2) + lane];
            ax += v * y.x; ay += v * y.y;
        }
    }

    float2 yr = Yin[w * (DHID / 2) + lane];
    float2 s  = ((const float2*)g_src)[w * (DHID / 2) + lane];
    float2 o;
    o.x = 0.5f * (yr.x + ax) + s.x;
    o.y = 0.5f * (yr.y + ay) + s.y;
    Yout[w * (DHID / 2) + lane] = o;
}

// ---------------------------------------------------------------------------
// Kernel 4: out = relu(Y) @ W2 + b2.
// ---------------------------------------------------------------------------
__global__ __launch_bounds__(256) void mlp2_kernel(
    const float* __restrict__ W2, const float* __restrict__ b2,
    float* __restrict__ out)
{
    __shared__ float w2s[64][41];
    __shared__ float ys[64][65];
    __shared__ float b2s[DOUT];

    const int tid = threadIdx.x;
    const int row0 = blockIdx.x * 64;

    for (int idx = tid; idx < DHID * DOUT; idx += 256)
        w2s[idx / DOUT][idx % DOUT] = W2[idx];
    if (tid < DOUT) b2s[tid] = b2[tid];

    #pragma unroll
    for (int i = 0; i < 16; i++) {
        int idx = tid + i * 256;
        int r = idx >> 6, c = idx & 63;
        int gr = row0 + r;
        ys[r][c] = (gr < N_NODES) ? fmaxf(g_Y0[gr * DHID + c], 0.f) : 0.f;
    }
    __syncthreads();

    const int row = tid >> 2;
    const int cg  = tid & 3;
    float acc[10];
    #pragma unroll
    for (int i = 0; i < 10; i++) acc[i] = b2s[cg * 10 + i];

    #pragma unroll 8
    for (int j = 0; j < DHID; j++) {
        float yv = ys[row][j];
        #pragma unroll
        for (int i = 0; i < 10; i++)
            acc[i] += yv * w2s[j][cg * 10 + i];
    }

    int gr = row0 + row;
    if (gr < N_NODES) {
        #pragma unroll
        for (int i = 0; i < 10; i++)
            out[gr * DOUT + cg * 10 + i] = acc[i];
    }
}

// ---------------------------------------------------------------------------
extern "C" void kernel_launch(void* const* d_in, const int* in_sizes, int n_in,
                              void* d_out, int out_size)
{
    const float* x     = (const float*)d_in[0];
    const int*   erow  = (const int*)  d_in[1];
    const int*   ecol  = (const int*)  d_in[2];
    const float* evalv = (const float*)d_in[3];
    const float* diag  = (const float*)d_in[4];
    const float* W1    = (const float*)d_in[5];
    const float* b1    = (const float*)d_in[6];
    const float* W2    = (const float*)d_in[7];
    const float* b2    = (const float*)d_in[8];
    float* out = (float*)d_out;

    build_rowptr_kernel<<<(N_NODES + 1 + 255) / 256, 256>>>(erow);
    pack_edges_kernel<<<(E_EDGES + 255) / 256, 256>>>(ecol, evalv);

    int gemm_blocks = (N_NODES + 63) / 64;
    gemm1_kernel<<<gemm_blocks, 256>>>(x, W1, b1, diag);

    int prop_blocks = N_NODES / ROWS_PER_BLOCK;   // 12500, exact
    for (int s = 0; s < PROP_STEPS; s++) {
        prop_kernel<<<prop_blocks, 256>>>(s & 1);
    }

    mlp2_kernel<<<gemm_blocks, 256>>>(W2, b2, out);
}

// round 6
// speedup vs baseline: 1.0851x; 1.0185x over previous
#include <cuda_runtime.h>
#include <cuda_bf16.h>

#define N_NODES 100000
#define E_EDGES 1600000
#define DIN     256
#define DHID    64
#define DOUT    40
#define PROP_STEPS 16

// Scratch (allocation-free rule: __device__ globals)
__device__ float g_Y0[N_NODES * DHID];
__device__ float g_Y1[N_NODES * DHID];
__device__ float g_src[N_NODES * DHID];
__device__ int2  g_epack[E_EDGES];          // packed (col, val_bits)
__device__ int   g_row_ptr[N_NODES + 1];

// ---------------------------------------------------------------------------
// Kernel 1: CSR row pointers from sorted edge_row via per-thread lower_bound
// ---------------------------------------------------------------------------
__global__ void build_rowptr_kernel(const int* __restrict__ edge_row) {
    int r = blockIdx.x * blockDim.x + threadIdx.x;
    if (r > N_NODES) return;
    int lo = 0, hi = E_EDGES;
    while (lo < hi) {
        int mid = (lo + hi) >> 1;
        if (edge_row[mid] < r) lo = mid + 1; else hi = mid;
    }
    g_row_ptr[r] = lo;
}

// ---------------------------------------------------------------------------
// Kernel 1b: pack (col, val) pairs
// ---------------------------------------------------------------------------
__global__ void pack_edges_kernel(const int* __restrict__ ecol,
                                  const float* __restrict__ evalv) {
    int i = blockIdx.x * blockDim.x + threadIdx.x;
    if (i < E_EDGES)
        g_epack[i] = make_int2(ecol[i], __float_as_int(evalv[i]));
}

// ---------------------------------------------------------------------------
// Kernel 2: h = x @ W1 + b1 ; Y0 = h ; src = 0.5 * diag * h
// ---------------------------------------------------------------------------
__global__ __launch_bounds__(256) void gemm1_kernel(
    const float* __restrict__ x, const float* __restrict__ W1,
    const float* __restrict__ b1, const float* __restrict__ diag)
{
    __shared__ float xs[64][33];
    __shared__ float ws[32][64];

    const int tid = threadIdx.x;
    const int ty = tid >> 4;
    const int tx = tid & 15;
    const int row0 = blockIdx.x * 64;

    float acc[4][4];
    #pragma unroll
    for (int i = 0; i < 4; i++)
        #pragma unroll
        for (int j = 0; j < 4; j++) acc[i][j] = 0.f;

    for (int k0 = 0; k0 < DIN; k0 += 32) {
        #pragma unroll
        for (int i = 0; i < 8; i++) {
            int idx = tid + i * 256;
            int r = idx >> 5, kk = idx & 31;
            int gr = row0 + r;
            xs[r][kk] = (gr < N_NODES) ? x[gr * DIN + k0 + kk] : 0.f;
        }
        #pragma unroll
        for (int i = 0; i < 8; i++) {
            int idx = tid + i * 256;
            int kk = idx >> 6, c = idx & 63;
            ws[kk][c] = W1[(k0 + kk) * DHID + c];
        }
        __syncthreads();

        #pragma unroll
        for (int kk = 0; kk < 32; kk++) {
            float a0 = xs[ty * 4 + 0][kk];
            float a1 = xs[ty * 4 + 1][kk];
            float a2 = xs[ty * 4 + 2][kk];
            float a3 = xs[ty * 4 + 3][kk];
            float w0 = ws[kk][tx * 4 + 0];
            float w1 = ws[kk][tx * 4 + 1];
            float w2 = ws[kk][tx * 4 + 2];
            float w3 = ws[kk][tx * 4 + 3];
            acc[0][0] += a0 * w0; acc[0][1] += a0 * w1; acc[0][2] += a0 * w2; acc[0][3] += a0 * w3;
            acc[1][0] += a1 * w0; acc[1][1] += a1 * w1; acc[1][2] += a1 * w2; acc[1][3] += a1 * w3;
            acc[2][0] += a2 * w0; acc[2][1] += a2 * w1; acc[2][2] += a2 * w2; acc[2][3] += a2 * w3;
            acc[3][0] += a3 * w0; acc[3][1] += a3 * w1; acc[3][2] += a3 * w2; acc[3][3] += a3 * w3;
        }
        __syncthreads();
    }

    #pragma unroll
    for (int i = 0; i < 4; i++) {
        int gr = row0 + ty * 4 + i;
        if (gr < N_NODES) {
            float dv = 0.5f * diag[gr];
            #pragma unroll
            for (int j = 0; j < 4; j++) {
                int c = tx * 4 + j;
                float h = acc[i][j] + b1[c];
                g_Y0[gr * DHID + c]  = h;
                g_src[gr * DHID + c] = dv * h;
            }
        }
    }
}

// ---------------------------------------------------------------------------
// Kernel 3: one propagation step. One warp per row, two half-warp edge slots.
// Lane layout: slot = lane>>4 (which edge of a pair), cg = lane&15 (4 columns
// via float4). Per edge-pair: 1 metadata LDG.64 + 1 gather LDG.128
// => 1 LDG/edge, ~2.5 L1tex wavefronts/edge, no divergence, no block sync.
// ---------------------------------------------------------------------------
__global__ __launch_bounds__(256) void prop_kernel(int phase)
{
    const float4* __restrict__ Yin4  = (const float4*)(phase ? g_Y1 : g_Y0);
    float4*       __restrict__ Yout4 = (float4*)      (phase ? g_Y0 : g_Y1);

    int w = (blockIdx.x * blockDim.x + threadIdx.x) >> 5;
    if (w >= N_NODES) return;
    const int lane = threadIdx.x & 31;
    const int slot = lane >> 4;     // 0 or 1: which edge of the pair
    const int cg   = lane & 15;     // column group: cols [4cg, 4cg+3]

    int e   = g_row_ptr[w];
    const int end = g_row_ptr[w + 1];

    float4 acc = make_float4(0.f, 0.f, 0.f, 0.f);

    // Main loop: 4 pairs = 8 edges, no clamping needed
    for (; e + 8 <= end; e += 8) {
        #pragma unroll
        for (int p = 0; p < 4; p++) {
            int2  m = g_epack[e + 2 * p + slot];
            float v = __int_as_float(m.y);
            float4 y = Yin4[m.x * (DHID / 4) + cg];
            acc.x += v * y.x; acc.y += v * y.y;
            acc.z += v * y.z; acc.w += v * y.w;
        }
    }
    // Tail: pairwise with clamped index (uniform control flow, v=0 if invalid)
    for (; e < end; e += 2) {
        int  idx   = e + slot;
        bool valid = idx < end;
        int2 m = g_epack[valid ? idx : end - 1];
        float v = valid ? __int_as_float(m.y) : 0.f;
        float4 y = Yin4[m.x * (DHID / 4) + cg];
        acc.x += v * y.x; acc.y += v * y.y;
        acc.z += v * y.z; acc.w += v * y.w;
    }

    // Combine the two edge-slot partial sums
    acc.x += __shfl_xor_sync(0xffffffffu, acc.x, 16);
    acc.y += __shfl_xor_sync(0xffffffffu, acc.y, 16);
    acc.z += __shfl_xor_sync(0xffffffffu, acc.z, 16);
    acc.w += __shfl_xor_sync(0xffffffffu, acc.w, 16);

    if (slot == 0) {
        float4 yr = Yin4[w * (DHID / 4) + cg];
        float4 s  = ((const float4*)g_src)[w * (DHID / 4) + cg];
        float4 o;
        o.x = 0.5f * (yr.x + acc.x) + s.x;
        o.y = 0.5f * (yr.y + acc.y) + s.y;
        o.z = 0.5f * (yr.z + acc.z) + s.z;
        o.w = 0.5f * (yr.w + acc.w) + s.w;
        Yout4[w * (DHID / 4) + cg] = o;
    }
}

// ---------------------------------------------------------------------------
// Kernel 4: out = relu(Y) @ W2 + b2.
// ---------------------------------------------------------------------------
__global__ __launch_bounds__(256) void mlp2_kernel(
    const float* __restrict__ W2, const float* __restrict__ b2,
    float* __restrict__ out)
{
    __shared__ float w2s[64][41];
    __shared__ float ys[64][65];
    __shared__ float b2s[DOUT];

    const int tid = threadIdx.x;
    const int row0 = blockIdx.x * 64;

    for (int idx = tid; idx < DHID * DOUT; idx += 256)
        w2s[idx / DOUT][idx % DOUT] = W2[idx];
    if (tid < DOUT) b2s[tid] = b2[tid];

    #pragma unroll
    for (int i = 0; i < 16; i++) {
        int idx = tid + i * 256;
        int r = idx >> 6, c = idx & 63;
        int gr = row0 + r;
        ys[r][c] = (gr < N_NODES) ? fmaxf(g_Y0[gr * DHID + c], 0.f) : 0.f;
    }
    __syncthreads();

    const int row = tid >> 2;
    const int cg  = tid & 3;
    float acc[10];
    #pragma unroll
    for (int i = 0; i < 10; i++) acc[i] = b2s[cg * 10 + i];

    #pragma unroll 8
    for (int j = 0; j < DHID; j++) {
        float yv = ys[row][j];
        #pragma unroll
        for (int i = 0; i < 10; i++)
            acc[i] += yv * w2s[j][cg * 10 + i];
    }

    int gr = row0 + row;
    if (gr < N_NODES) {
        #pragma unroll
        for (int i = 0; i < 10; i++)
            out[gr * DOUT + cg * 10 + i] = acc[i];
    }
}

// ---------------------------------------------------------------------------
extern "C" void kernel_launch(void* const* d_in, const int* in_sizes, int n_in,
                              void* d_out, int out_size)
{
    const float* x     = (const float*)d_in[0];
    const int*   erow  = (const int*)  d_in[1];
    const int*   ecol  = (const int*)  d_in[2];
    const float* evalv = (const float*)d_in[3];
    const float* diag  = (const float*)d_in[4];
    const float* W1    = (const float*)d_in[5];
    const float* b1    = (const float*)d_in[6];
    const float* W2    = (const float*)d_in[7];
    const float* b2    = (const float*)d_in[8];
    float* out = (float*)d_out;

    build_rowptr_kernel<<<(N_NODES + 1 + 255) / 256, 256>>>(erow);
    pack_edges_kernel<<<(E_EDGES + 255) / 256, 256>>>(ecol, evalv);

    int gemm_blocks = (N_NODES + 63) / 64;
    gemm1_kernel<<<gemm_blocks, 256>>>(x, W1, b1, diag);

    int prop_blocks = (N_NODES * 32 + 255) / 256;   // one warp per row
    for (int s = 0; s < PROP_STEPS; s++) {
        prop_kernel<<<prop_blocks, 256>>>(s & 1);
    }

    mlp2_kernel<<<gemm_blocks, 256>>>(W2, b2, out);
}

// round 7
// speedup vs baseline: 1.1904x; 1.0970x over previous
#include <cuda_runtime.h>
#include <cuda_bf16.h>

#define N_NODES 100000
#define E_EDGES 1600000
#define DIN     256
#define DHID    64
#define DOUT    40
#define PROP_STEPS 16

// Scratch (allocation-free rule: __device__ globals)
__device__ float g_Y0[N_NODES * DHID];
__device__ float g_Y1[N_NODES * DHID];
__device__ float g_src[N_NODES * DHID];
__device__ int2  g_epack[E_EDGES];          // packed (col, val_bits)
__device__ int   g_row_ptr[N_NODES + 1];

// ---------------------------------------------------------------------------
// Kernel 1: CSR row pointers from sorted edge_row via per-thread lower_bound
// ---------------------------------------------------------------------------
__global__ void build_rowptr_kernel(const int* __restrict__ edge_row) {
    int r = blockIdx.x * blockDim.x + threadIdx.x;
    if (r > N_NODES) return;
    int lo = 0, hi = E_EDGES;
    while (lo < hi) {
        int mid = (lo + hi) >> 1;
        if (edge_row[mid] < r) lo = mid + 1; else hi = mid;
    }
    g_row_ptr[r] = lo;
}

// ---------------------------------------------------------------------------
// Kernel 1b: pack (col, val) pairs
// ---------------------------------------------------------------------------
__global__ void pack_edges_kernel(const int* __restrict__ ecol,
                                  const float* __restrict__ evalv) {
    int i = blockIdx.x * blockDim.x + threadIdx.x;
    if (i < E_EDGES)
        g_epack[i] = make_int2(ecol[i], __float_as_int(evalv[i]));
}

// ---------------------------------------------------------------------------
// Kernel 2: h = x @ W1 + b1 ; Y0 = h ; src = 0.5 * diag * h
// ---------------------------------------------------------------------------
__global__ __launch_bounds__(256) void gemm1_kernel(
    const float* __restrict__ x, const float* __restrict__ W1,
    const float* __restrict__ b1, const float* __restrict__ diag)
{
    __shared__ float xs[64][33];
    __shared__ float ws[32][64];

    const int tid = threadIdx.x;
    const int ty = tid >> 4;
    const int tx = tid & 15;
    const int row0 = blockIdx.x * 64;

    float acc[4][4];
    #pragma unroll
    for (int i = 0; i < 4; i++)
        #pragma unroll
        for (int j = 0; j < 4; j++) acc[i][j] = 0.f;

    for (int k0 = 0; k0 < DIN; k0 += 32) {
        #pragma unroll
        for (int i = 0; i < 8; i++) {
            int idx = tid + i * 256;
            int r = idx >> 5, kk = idx & 31;
            int gr = row0 + r;
            xs[r][kk] = (gr < N_NODES) ? x[gr * DIN + k0 + kk] : 0.f;
        }
        #pragma unroll
        for (int i = 0; i < 8; i++) {
            int idx = tid + i * 256;
            int kk = idx >> 6, c = idx & 63;
            ws[kk][c] = W1[(k0 + kk) * DHID + c];
        }
        __syncthreads();

        #pragma unroll
        for (int kk = 0; kk < 32; kk++) {
            float a0 = xs[ty * 4 + 0][kk];
            float a1 = xs[ty * 4 + 1][kk];
            float a2 = xs[ty * 4 + 2][kk];
            float a3 = xs[ty * 4 + 3][kk];
            float w0 = ws[kk][tx * 4 + 0];
            float w1 = ws[kk][tx * 4 + 1];
            float w2 = ws[kk][tx * 4 + 2];
            float w3 = ws[kk][tx * 4 + 3];
            acc[0][0] += a0 * w0; acc[0][1] += a0 * w1; acc[0][2] += a0 * w2; acc[0][3] += a0 * w3;
            acc[1][0] += a1 * w0; acc[1][1] += a1 * w1; acc[1][2] += a1 * w2; acc[1][3] += a1 * w3;
            acc[2][0] += a2 * w0; acc[2][1] += a2 * w1; acc[2][2] += a2 * w2; acc[2][3] += a2 * w3;
            acc[3][0] += a3 * w0; acc[3][1] += a3 * w1; acc[3][2] += a3 * w2; acc[3][3] += a3 * w3;
        }
        __syncthreads();
    }

    #pragma unroll
    for (int i = 0; i < 4; i++) {
        int gr = row0 + ty * 4 + i;
        if (gr < N_NODES) {
            float dv = 0.5f * diag[gr];
            #pragma unroll
            for (int j = 0; j < 4; j++) {
                int c = tx * 4 + j;
                float h = acc[i][j] + b1[c];
                g_Y0[gr * DHID + c]  = h;
                g_src[gr * DHID + c] = dv * h;
            }
        }
    }
}

// ---------------------------------------------------------------------------
// Kernel 3: one propagation step. One warp per row; lane owns 2 columns.
// Metadata: ONE coalesced LDG.64 per 32 edges (int2 per lane), then
// register broadcasts via shfl (26-cyc, off the LSU/L1tex path).
// Inner loop: unroll 4, predicated v=0 tail, uniform control flow.
// Per edge: 1 gather LDG.64 + 2 SHFL + 2 FFMA. No smem, no block sync.
// ---------------------------------------------------------------------------
__global__ __launch_bounds__(256) void prop_kernel(int phase)
{
    const float2* __restrict__ Yin  = (const float2*)(phase ? g_Y1 : g_Y0);
    float2*       __restrict__ Yout = (float2*)      (phase ? g_Y0 : g_Y1);

    int w = (blockIdx.x * blockDim.x + threadIdx.x) >> 5;
    if (w >= N_NODES) return;
    const int lane = threadIdx.x & 31;

    const int e0  = g_row_ptr[w];
    const int end = g_row_ptr[w + 1];

    float ax = 0.f, ay = 0.f;

    for (int base = e0; base < end; base += 32) {
        const int n = end - base;                 // >= 1, may exceed 32
        const int nc = (n < 32) ? n : 32;         // edges in this batch
        // one coalesced metadata load: lane i holds edge base+i (clamped)
        int2 m = g_epack[base + ((lane < nc) ? lane : (nc - 1))];

        const int n4 = (nc + 3) & ~3;             // <= 32
        for (int j = 0; j < n4; j += 4) {
            #pragma unroll
            for (int q = 0; q < 4; q++) {
                int jj = j + q;
                int col = __shfl_sync(0xffffffffu, m.x, jj);
                int vb  = __shfl_sync(0xffffffffu, m.y, jj);
                float v = (jj < nc) ? __int_as_float(vb) : 0.f;
                float2 y = Yin[col * (DHID / 2) + lane];
                ax += v * y.x;
                ay += v * y.y;
            }
        }
    }

    float2 yr = Yin[w * (DHID / 2) + lane];
    float2 s  = ((const float2*)g_src)[w * (DHID / 2) + lane];
    float2 o;
    o.x = 0.5f * (yr.x + ax) + s.x;
    o.y = 0.5f * (yr.y + ay) + s.y;
    Yout[w * (DHID / 2) + lane] = o;
}

// ---------------------------------------------------------------------------
// Kernel 4: out = relu(Y) @ W2 + b2.
// ---------------------------------------------------------------------------
__global__ __launch_bounds__(256) void mlp2_kernel(
    const float* __restrict__ W2, const float* __restrict__ b2,
    float* __restrict__ out)
{
    __shared__ float w2s[64][41];
    __shared__ float ys[64][65];
    __shared__ float b2s[DOUT];

    const int tid = threadIdx.x;
    const int row0 = blockIdx.x * 64;

    for (int idx = tid; idx < DHID * DOUT; idx += 256)
        w2s[idx / DOUT][idx % DOUT] = W2[idx];
    if (tid < DOUT) b2s[tid] = b2[tid];

    #pragma unroll
    for (int i = 0; i < 16; i++) {
        int idx = tid + i * 256;
        int r = idx >> 6, c = idx & 63;
        int gr = row0 + r;
        ys[r][c] = (gr < N_NODES) ? fmaxf(g_Y0[gr * DHID + c], 0.f) : 0.f;
    }
    __syncthreads();

    const int row = tid >> 2;
    const int cg  = tid & 3;
    float acc[10];
    #pragma unroll
    for (int i = 0; i < 10; i++) acc[i] = b2s[cg * 10 + i];

    #pragma unroll 8
    for (int j = 0; j < DHID; j++) {
        float yv = ys[row][j];
        #pragma unroll
        for (int i = 0; i < 10; i++)
            acc[i] += yv * w2s[j][cg * 10 + i];
    }

    int gr = row0 + row;
    if (gr < N_NODES) {
        #pragma unroll
        for (int i = 0; i < 10; i++)
            out[gr * DOUT + cg * 10 + i] = acc[i];
    }
}

// ---------------------------------------------------------------------------
extern "C" void kernel_launch(void* const* d_in, const int* in_sizes, int n_in,
                              void* d_out, int out_size)
{
    const float* x     = (const float*)d_in[0];
    const int*   erow  = (const int*)  d_in[1];
    const int*   ecol  = (const int*)  d_in[2];
    const float* evalv = (const float*)d_in[3];
    const float* diag  = (const float*)d_in[4];
    const float* W1    = (const float*)d_in[5];
    const float* b1    = (const float*)d_in[6];
    const float* W2    = (const float*)d_in[7];
    const float* b2    = (const float*)d_in[8];
    float* out = (float*)d_out;

    build_rowptr_kernel<<<(N_NODES + 1 + 255) / 256, 256>>>(erow);
    pack_edges_kernel<<<(E_EDGES + 255) / 256, 256>>>(ecol, evalv);

    int gemm_blocks = (N_NODES + 63) / 64;
    gemm1_kernel<<<gemm_blocks, 256>>>(x, W1, b1, diag);

    int prop_blocks = (N_NODES * 32 + 255) / 256;   // one warp per row
    for (int s = 0; s < PROP_STEPS; s++) {
        prop_kernel<<<prop_blocks, 256>>>(s & 1);
    }

    mlp2_kernel<<<gemm_blocks, 256>>>(W2, b2, out);
}

// round 8
// speedup vs baseline: 1.3714x; 1.1520x over previous
#include <cuda_runtime.h>
#include <cuda_bf16.h>

#define N_NODES 100000
#define E_EDGES 1600000
#define DIN     256
#define DHID    64
#define DOUT    40
#define PROP_STEPS 16

// Scratch (allocation-free rule: __device__ globals)
__device__ float g_Y0[N_NODES * DHID];
__device__ float g_Y1[N_NODES * DHID];
__device__ float g_src[N_NODES * DHID];
__device__ int   g_row_ptr[N_NODES + 1];

// ---------------------------------------------------------------------------
// Kernel 1: CSR row pointers from sorted edge_row via per-thread lower_bound
// ---------------------------------------------------------------------------
__global__ void build_rowptr_kernel(const int* __restrict__ edge_row) {
    int r = blockIdx.x * blockDim.x + threadIdx.x;
    if (r > N_NODES) return;
    int lo = 0, hi = E_EDGES;
    while (lo < hi) {
        int mid = (lo + hi) >> 1;
        if (edge_row[mid] < r) lo = mid + 1; else hi = mid;
    }
    g_row_ptr[r] = lo;
}

// ---------------------------------------------------------------------------
// bf16 hi/lo split helpers for the tensor-core GEMM
// ---------------------------------------------------------------------------
__device__ __forceinline__ void split2(float a, float b, unsigned& hi, unsigned& lo) {
    __nv_bfloat16 ha = __float2bfloat16_rn(a);
    __nv_bfloat16 hb = __float2bfloat16_rn(b);
    float ra = a - __bfloat162float(ha);
    float rb = b - __bfloat162float(hb);
    __nv_bfloat162 H = __halves2bfloat162(ha, hb);                 // .x = a (k even)
    __nv_bfloat162 L = __halves2bfloat162(__float2bfloat16_rn(ra),
                                          __float2bfloat16_rn(rb));
    hi = reinterpret_cast<unsigned&>(H);
    lo = reinterpret_cast<unsigned&>(L);
}

__device__ __forceinline__ void mma_bf16(float* c, const unsigned* a,
                                         unsigned b0, unsigned b1) {
    asm volatile(
        "mma.sync.aligned.m16n8k16.row.col.f32.bf16.bf16.f32 "
        "{%0,%1,%2,%3}, {%4,%5,%6,%7}, {%8,%9}, {%0,%1,%2,%3};"
        : "+f"(c[0]), "+f"(c[1]), "+f"(c[2]), "+f"(c[3])
        : "r"(a[0]), "r"(a[1]), "r"(a[2]), "r"(a[3]), "r"(b0), "r"(b1));
}

// ---------------------------------------------------------------------------
// Kernel 2 (tensor): h = x @ W1 + b1 ; Y0 = h ; src = 0.5 * diag * h
// Block = 128 rows, 8 warps; warp w owns rows [w*16, w*16+16) x all 64 cols.
// 3-term bf16 split (hi*hi + hi*lo + lo*hi) ~ fp32 precision (~1e-6 rel).
// W1 staged in smem per 128-k chunk, packed as (k,k+1) bf162 pairs with
// pad-to-72 so B-fragment LDS is bank-conflict-free.
// ---------------------------------------------------------------------------
__global__ __launch_bounds__(256) void gemm1_tensor_kernel(
    const float* __restrict__ x, const float* __restrict__ W1,
    const float* __restrict__ b1, const float* __restrict__ diag)
{
    __shared__ unsigned sBhi[64][72];   // pair-row (k/2 within chunk), col n
    __shared__ unsigned sBlo[64][72];

    const int tid  = threadIdx.x;
    const int w    = tid >> 5;
    const int lane = tid & 31;
    const int g    = lane >> 2;     // 0..7
    const int tc   = lane & 3;      // 0..3

    const int rowbase = blockIdx.x * 128 + w * 16;
    const int r0 = rowbase + g;
    const int r1 = rowbase + g + 8;
    const int r0c = (r0 < N_NODES) ? r0 : N_NODES - 1;   // clamped for loads
    const int r1c = (r1 < N_NODES) ? r1 : N_NODES - 1;

    const float* xrow0 = x + (size_t)r0c * DIN;
    const float* xrow1 = x + (size_t)r1c * DIN;

    float c[8][4];
    #pragma unroll
    for (int nt = 0; nt < 8; nt++)
        #pragma unroll
        for (int i = 0; i < 4; i++) c[nt][i] = 0.f;

    for (int chunk = 0; chunk < 2; chunk++) {
        const int k0 = chunk * 128;
        __syncthreads();
        // stage + split W1[k0..k0+127][0..63] into packed bf162 pairs
        for (int idx = tid; idx < 64 * 64; idx += 256) {
            int pr  = idx >> 6;          // pair-row 0..63
            int col = idx & 63;
            float w0 = W1[(k0 + 2 * pr)     * DHID + col];
            float w1 = W1[(k0 + 2 * pr + 1) * DHID + col];
            unsigned hi, lo;
            split2(w0, w1, hi, lo);
            sBhi[pr][col] = hi;
            sBlo[pr][col] = lo;
        }
        __syncthreads();

        #pragma unroll
        for (int j = 0; j < 8; j++) {            // 8 k16-steps per chunk
            const int kg = k0 + j * 16;
            // A fragments (row-major m16k16), hi/lo split
            float2 f00 = *(const float2*)(xrow0 + kg + 2 * tc);
            float2 f10 = *(const float2*)(xrow1 + kg + 2 * tc);
            float2 f01 = *(const float2*)(xrow0 + kg + 2 * tc + 8);
            float2 f11 = *(const float2*)(xrow1 + kg + 2 * tc + 8);
            unsigned ahi[4], alo[4];
            split2(f00.x, f00.y, ahi[0], alo[0]);
            split2(f10.x, f10.y, ahi[1], alo[1]);
            split2(f01.x, f01.y, ahi[2], alo[2]);
            split2(f11.x, f11.y, ahi[3], alo[3]);

            const int j8 = j * 8;
            #pragma unroll
            for (int nt = 0; nt < 8; nt++) {
                const int n0 = nt * 8;
                unsigned bh0 = sBhi[j8 + tc][n0 + g];
                unsigned bh1 = sBhi[j8 + tc + 4][n0 + g];
                unsigned bl0 = sBlo[j8 + tc][n0 + g];
                unsigned bl1 = sBlo[j8 + tc + 4][n0 + g];
                mma_bf16(c[nt], ahi, bh0, bh1);   // hi*hi
                mma_bf16(c[nt], ahi, bl0, bl1);   // hi*lo
                mma_bf16(c[nt], alo, bh0, bh1);   // lo*hi
            }
        }
    }

    // Epilogue: bias, write Y0 and src
    const float dv0 = (r0 < N_NODES) ? 0.5f * diag[r0] : 0.f;
    const float dv1 = (r1 < N_NODES) ? 0.5f * diag[r1] : 0.f;
    #pragma unroll
    for (int nt = 0; nt < 8; nt++) {
        const int col = nt * 8 + 2 * tc;
        float bb0 = b1[col], bb1 = b1[col + 1];
        if (r0 < N_NODES) {
            float h0 = c[nt][0] + bb0;
            float h1 = c[nt][1] + bb1;
            g_Y0[r0 * DHID + col]      = h0;
            g_Y0[r0 * DHID + col + 1]  = h1;
            g_src[r0 * DHID + col]     = dv0 * h0;
            g_src[r0 * DHID + col + 1] = dv0 * h1;
        }
        if (r1 < N_NODES) {
            float h2 = c[nt][2] + bb0;
            float h3 = c[nt][3] + bb1;
            g_Y0[r1 * DHID + col]      = h2;
            g_Y0[r1 * DHID + col + 1]  = h3;
            g_src[r1 * DHID + col]     = dv1 * h2;
            g_src[r1 * DHID + col + 1] = dv1 * h3;
        }
    }
}

// ---------------------------------------------------------------------------
// Kernel 3: one propagation step (exact R2 version — best measured).
// One warp per row; lane owns 2 columns; 4-edge unroll for MLP.
// ---------------------------------------------------------------------------
__global__ __launch_bounds__(256) void prop_kernel(
    const int* __restrict__ ecol, const float* __restrict__ evalv, int phase)
{
    const float* __restrict__ Yin  = phase ? g_Y1 : g_Y0;
    float*       __restrict__ Yout = phase ? g_Y0 : g_Y1;

    int w = (blockIdx.x * blockDim.x + threadIdx.x) >> 5;
    if (w >= N_NODES) return;
    int lane = threadIdx.x & 31;

    int e   = g_row_ptr[w];
    int end = g_row_ptr[w + 1];

    float ax = 0.f, ay = 0.f;

    for (; e + 4 <= end; e += 4) {
        int   c0 = ecol[e],     c1 = ecol[e + 1], c2 = ecol[e + 2], c3 = ecol[e + 3];
        float v0 = evalv[e],    v1 = evalv[e + 1], v2 = evalv[e + 2], v3 = evalv[e + 3];
        float2 y0 = *(const float2*)&Yin[c0 * DHID + lane * 2];
        float2 y1 = *(const float2*)&Yin[c1 * DHID + lane * 2];
        float2 y2 = *(const float2*)&Yin[c2 * DHID + lane * 2];
        float2 y3 = *(const float2*)&Yin[c3 * DHID + lane * 2];
        ax += v0 * y0.x + v1 * y1.x + v2 * y2.x + v3 * y3.x;
        ay += v0 * y0.y + v1 * y1.y + v2 * y2.y + v3 * y3.y;
    }
    for (; e < end; e++) {
        int   c = ecol[e];
        float v = evalv[e];
        float2 y = *(const float2*)&Yin[c * DHID + lane * 2];
        ax += v * y.x;
        ay += v * y.y;
    }

    float2 yr = *(const float2*)&Yin[w * DHID + lane * 2];
    float2 s  = *(const float2*)&g_src[w * DHID + lane * 2];
    float2 o;
    o.x = 0.5f * (yr.x + ax) + s.x;
    o.y = 0.5f * (yr.y + ay) + s.y;
    *(float2*)&Yout[w * DHID + lane * 2] = o;
}

// ---------------------------------------------------------------------------
// Kernel 4: out = relu(Y) @ W2 + b2.
// ---------------------------------------------------------------------------
__global__ __launch_bounds__(256) void mlp2_kernel(
    const float* __restrict__ W2, const float* __restrict__ b2,
    float* __restrict__ out)
{
    __shared__ float w2s[64][41];
    __shared__ float ys[64][65];
    __shared__ float b2s[DOUT];

    const int tid = threadIdx.x;
    const int row0 = blockIdx.x * 64;

    for (int idx = tid; idx < DHID * DOUT; idx += 256)
        w2s[idx / DOUT][idx % DOUT] = W2[idx];
    if (tid < DOUT) b2s[tid] = b2[tid];

    #pragma unroll
    for (int i = 0; i < 16; i++) {
        int idx = tid + i * 256;
        int r = idx >> 6, c = idx & 63;
        int gr = row0 + r;
        ys[r][c] = (gr < N_NODES) ? fmaxf(g_Y0[gr * DHID + c], 0.f) : 0.f;
    }
    __syncthreads();

    const int row = tid >> 2;
    const int cg  = tid & 3;
    float acc[10];
    #pragma unroll
    for (int i = 0; i < 10; i++) acc[i] = b2s[cg * 10 + i];

    #pragma unroll 8
    for (int j = 0; j < DHID; j++) {
        float yv = ys[row][j];
        #pragma unroll
        for (int i = 0; i < 10; i++)
            acc[i] += yv * w2s[j][cg * 10 + i];
    }

    int gr = row0 + row;
    if (gr < N_NODES) {
        #pragma unroll
        for (int i = 0; i < 10; i++)
            out[gr * DOUT + cg * 10 + i] = acc[i];
    }
}

// ---------------------------------------------------------------------------
extern "C" void kernel_launch(void* const* d_in, const int* in_sizes, int n_in,
                              void* d_out, int out_size)
{
    const float* x     = (const float*)d_in[0];
    const int*   erow  = (const int*)  d_in[1];
    const int*   ecol  = (const int*)  d_in[2];
    const float* evalv = (const float*)d_in[3];
    const float* diag  = (const float*)d_in[4];
    const float* W1    = (const float*)d_in[5];
    const float* b1    = (const float*)d_in[6];
    const float* W2    = (const float*)d_in[7];
    const float* b2    = (const float*)d_in[8];
    float* out = (float*)d_out;

    build_rowptr_kernel<<<(N_NODES + 1 + 255) / 256, 256>>>(erow);

    int gemm_blocks = (N_NODES + 127) / 128;
    gemm1_tensor_kernel<<<gemm_blocks, 256>>>(x, W1, b1, diag);

    int prop_blocks = (N_NODES * 32 + 255) / 256;   // one warp per row
    for (int s = 0; s < PROP_STEPS; s++) {
        prop_kernel<<<prop_blocks, 256>>>(ecol, evalv, s & 1);
    }

    int mlp_blocks = (N_NODES + 63) / 64;
    mlp2_kernel<<<mlp_blocks, 256>>>(W2, b2, out);
}